// round 2
// baseline (speedup 1.0000x reference)
#include <cuda_runtime.h>
#include <cuda_bf16.h>

// Problem constants
#define NB      32768
#define DD      16
#define CH1     64
#define CH2     32
#define CHO     64
#define RR      64

#define WT_PITCH 68   // wT[32][68]   : pad so scatter-store is only 4-way conflicted, float4 reads aligned
#define P_PITCH  65   // ps[64][65]   : conflict-free scalar access both directions

__global__ __launch_bounds__(256, 5)
void cp_tp_kernel(const float* __restrict__ x1,
                  const float* __restrict__ x2,
                  const float* __restrict__ w,
                  const float* __restrict__ Am,
                  const float* __restrict__ Bm,
                  const float* __restrict__ Cm,
                  float* __restrict__ out)
{
    __shared__ float x1s[DD * CH1];           // 1024
    __shared__ float x2s[DD * CH2];           // 512
    __shared__ float wTs[CH2 * WT_PITCH];     // 2176  wT[v][o]
    __shared__ float t2Ts[CH2 * RR];          // 2048  t2T[v][r]
    __shared__ float ps[RR * P_PITCH];        // 4160  p[r][o]
    __shared__ float Cs[DD * RR];             // 1024  C[c][r]

    const int b = blockIdx.x;
    const int t = threadIdx.x;

    const float* __restrict__ x1g = x1 + (size_t)b * (DD * CH1);
    const float* __restrict__ x2g = x2 + (size_t)b * (DD * CH2);
    const float* __restrict__ wg  = w  + (size_t)b * (CHO * CH2);

    // ---- stage 0: load x1, x2, C (direct), w (transposed) ----
#pragma unroll
    for (int j = 0; j < 4; j++) x1s[t + j * 256] = x1g[t + j * 256];
#pragma unroll
    for (int j = 0; j < 2; j++) x2s[t + j * 256] = x2g[t + j * 256];
#pragma unroll
    for (int j = 0; j < 4; j++) Cs[t + j * 256] = __ldg(&Cm[t + j * 256]);
#pragma unroll
    for (int j = 0; j < 8; j++) {
        int idx = t + j * 256;            // coalesced global read
        int o = idx >> 5;                 // w[b][o][v], v contiguous
        int v = idx & 31;
        wTs[v * WT_PITCH + o] = wg[idx];
    }
    __syncthreads();

    // ---- stage 1: t2[r,v] = sum_i B[i,r] * x2[i,v]; store transposed t2T[v][r] ----
    {
        const int r  = t & 63;
        const int vg = t >> 6;
        const int v0 = vg * 8;
        float acc[8];
#pragma unroll
        for (int k = 0; k < 8; k++) acc[k] = 0.f;
#pragma unroll
        for (int i = 0; i < DD; i++) {
            float bb = __ldg(&Bm[i * RR + r]);                 // coalesced, L1-resident
            float4 xa = *(const float4*)&x2s[i * CH2 + v0];     // broadcast
            float4 xb = *(const float4*)&x2s[i * CH2 + v0 + 4]; // broadcast
            acc[0] = fmaf(bb, xa.x, acc[0]);
            acc[1] = fmaf(bb, xa.y, acc[1]);
            acc[2] = fmaf(bb, xa.z, acc[2]);
            acc[3] = fmaf(bb, xa.w, acc[3]);
            acc[4] = fmaf(bb, xb.x, acc[4]);
            acc[5] = fmaf(bb, xb.y, acc[5]);
            acc[6] = fmaf(bb, xb.z, acc[6]);
            acc[7] = fmaf(bb, xb.w, acc[7]);
        }
#pragma unroll
        for (int k = 0; k < 8; k++) t2Ts[(v0 + k) * RR + r] = acc[k]; // conflict-free
    }
    __syncthreads();

    // ---- stage 2: t1[r,o], t3[r,o] for 16 o-columns per thread; p = t1*t3 ----
    {
        const int r  = t & 63;
        const int oc = t >> 6;
        const int o0 = oc * 16;

        float t1a[16], t3a[16];
#pragma unroll
        for (int k = 0; k < 16; k++) { t1a[k] = 0.f; t3a[k] = 0.f; }

        // t1[r,o] = sum_i A[i,r] * x1[i,o]
#pragma unroll
        for (int i = 0; i < DD; i++) {
            float a = __ldg(&Am[i * RR + r]);                  // coalesced, L1-resident
#pragma unroll
            for (int j = 0; j < 4; j++) {
                float4 xv = *(const float4*)&x1s[i * CH1 + o0 + j * 4]; // broadcast
                t1a[j * 4 + 0] = fmaf(a, xv.x, t1a[j * 4 + 0]);
                t1a[j * 4 + 1] = fmaf(a, xv.y, t1a[j * 4 + 1]);
                t1a[j * 4 + 2] = fmaf(a, xv.z, t1a[j * 4 + 2]);
                t1a[j * 4 + 3] = fmaf(a, xv.w, t1a[j * 4 + 3]);
            }
        }

        // t3[r,o] = sum_v t2[r,v] * w[o,v]
#pragma unroll 8
        for (int v = 0; v < CH2; v++) {
            float t2v = t2Ts[v * RR + r];                      // conflict-free
#pragma unroll
            for (int j = 0; j < 4; j++) {
                float4 wv = *(const float4*)&wTs[v * WT_PITCH + o0 + j * 4]; // broadcast
                t3a[j * 4 + 0] = fmaf(t2v, wv.x, t3a[j * 4 + 0]);
                t3a[j * 4 + 1] = fmaf(t2v, wv.y, t3a[j * 4 + 1]);
                t3a[j * 4 + 2] = fmaf(t2v, wv.z, t3a[j * 4 + 2]);
                t3a[j * 4 + 3] = fmaf(t2v, wv.w, t3a[j * 4 + 3]);
            }
        }

#pragma unroll
        for (int k = 0; k < 16; k++)
            ps[r * P_PITCH + o0 + k] = t1a[k] * t3a[k];        // conflict-free scalar
    }
    __syncthreads();

    // ---- stage 3: out[c,o] = sum_r C[c,r] * p[r,o] ----
    {
        const int o4 = t & 15;          // owns o = o4*4 .. o4*4+3
        const int c  = t >> 4;          // 16 c values
        float acc0 = 0.f, acc1 = 0.f, acc2 = 0.f, acc3 = 0.f;
#pragma unroll 16
        for (int r = 0; r < RR; r++) {
            float cc = Cs[c * RR + r];                         // smem broadcast (2 rows/warp)
            const float* pr = &ps[r * P_PITCH + o4 * 4];
            acc0 = fmaf(cc, pr[0], acc0);
            acc1 = fmaf(cc, pr[1], acc1);
            acc2 = fmaf(cc, pr[2], acc2);
            acc3 = fmaf(cc, pr[3], acc3);
        }
        float4 res = make_float4(acc0, acc1, acc2, acc3);
        *(float4*)&out[(size_t)b * (DD * CHO) + c * CHO + o4 * 4] = res;  // coalesced
    }
}

extern "C" void kernel_launch(void* const* d_in, const int* in_sizes, int n_in,
                              void* d_out, int out_size)
{
    const float* x1 = (const float*)d_in[0];
    const float* x2 = (const float*)d_in[1];
    const float* w  = (const float*)d_in[2];
    const float* Am = (const float*)d_in[3];
    const float* Bm = (const float*)d_in[4];
    const float* Cm = (const float*)d_in[5];
    float* out = (float*)d_out;

    cp_tp_kernel<<<NB, 256>>>(x1, x2, w, Am, Bm, Cm, out);
}

// round 3
// speedup vs baseline: 2.2725x; 2.2725x over previous
#include <cuda_runtime.h>
#include <cuda_bf16.h>
#include <cstdint>

// Problem constants
#define NB      32768
#define DD      16
#define CH1     64
#define CH2     32
#define CHO     64
#define RR      64

// smem pitches (in 4-byte words) — chosen for conflict-free fragment gathers
#define P1 72   // x1s, p_hi/p_lo pitch:  (72*k) % 32 = 8k -> 8*tig + gid distinct
#define P2 40   // x2s pitch
#define PW 36   // ws, t2 pitch: (36*r) % 32 = 4r -> 4*gid + tig distinct

// smem word offsets
#define OFF_X1   0                    // 16*72  = 1152
#define OFF_X2   (OFF_X1 + 16*P1)     // 16*40  = 640
#define OFF_W    (OFF_X2 + 16*P2)     // 64*36  = 2304
#define OFF_T2H  (OFF_W  + 64*PW)     // 64*36  = 2304
#define OFF_T2L  (OFF_T2H + 64*PW)    // 64*36  = 2304
#define OFF_PH   (OFF_T2L + 64*PW)    // 64*72  = 4608
#define OFF_PL   (OFF_PH + 64*P1)     // 64*72  = 4608
#define SMEM_WORDS (OFF_PL + 64*P1)   // 17920 words = 71680 bytes

__device__ __forceinline__ unsigned f2tf(float x) {
    unsigned r;
    asm("cvt.rna.tf32.f32 %0, %1;" : "=r"(r) : "f"(x));
    return r;
}

__device__ __forceinline__ void mma_tf32(float* d, const unsigned* a, const unsigned* b) {
    asm volatile(
        "mma.sync.aligned.m16n8k8.row.col.f32.tf32.tf32.f32 "
        "{%0,%1,%2,%3}, {%4,%5,%6,%7}, {%8,%9}, {%0,%1,%2,%3};\n"
        : "+f"(d[0]), "+f"(d[1]), "+f"(d[2]), "+f"(d[3])
        : "r"(a[0]), "r"(a[1]), "r"(a[2]), "r"(a[3]), "r"(b[0]), "r"(b[1]));
}

__global__ __launch_bounds__(128, 3)
void cp_tp_tf32(const float* __restrict__ x1,
                const float* __restrict__ x2,
                const float* __restrict__ w,
                const float* __restrict__ Am,
                const float* __restrict__ Bm,
                const float* __restrict__ Cm,
                float* __restrict__ out)
{
    extern __shared__ unsigned sm[];
    unsigned* x1s  = sm + OFF_X1;
    unsigned* x2s  = sm + OFF_X2;
    unsigned* ws   = sm + OFF_W;
    unsigned* t2hi = sm + OFF_T2H;
    unsigned* t2lo = sm + OFF_T2L;
    unsigned* phi  = sm + OFF_PH;
    unsigned* plo  = sm + OFF_PL;

    const int b    = blockIdx.x;
    const int t    = threadIdx.x;
    const int lane = t & 31;
    const int wp   = t >> 5;        // warp 0..3, owns r-tile rows [wp*16, wp*16+16)
    const int gid  = lane >> 2;     // 0..7
    const int tig  = lane & 3;      // 0..3

    const float* __restrict__ x1g = x1 + (size_t)b * (DD * CH1);
    const float* __restrict__ x2g = x2 + (size_t)b * (DD * CH2);
    const float* __restrict__ wg  = w  + (size_t)b * (CHO * CH2);

    // ---- stage 0: load + convert inputs to tf32 in smem ----
#pragma unroll
    for (int j = 0; j < 8; j++) {               // x1: 16 x 64
        int idx = t + j * 128;
        x1s[(idx >> 6) * P1 + (idx & 63)] = f2tf(x1g[idx]);
    }
#pragma unroll
    for (int j = 0; j < 4; j++) {               // x2: 16 x 32
        int idx = t + j * 128;
        x2s[(idx >> 5) * P2 + (idx & 31)] = f2tf(x2g[idx]);
    }
#pragma unroll
    for (int j = 0; j < 16; j++) {              // w: 64 x 32 -> ws[o][v]
        int idx = t + j * 128;
        ws[(idx >> 5) * PW + (idx & 31)] = f2tf(wg[idx]);
    }
    __syncthreads();

    // ---- stage A: t1 (r-tile x 64 o, K=16) and t2 (r-tile x 32 v, K=16) ----
    float t1a[8][4];
    float t2a[4][4];
#pragma unroll
    for (int n = 0; n < 8; n++)
#pragma unroll
        for (int j = 0; j < 4; j++) t1a[n][j] = 0.f;
#pragma unroll
    for (int n = 0; n < 4; n++)
#pragma unroll
        for (int j = 0; j < 4; j++) t2a[n][j] = 0.f;

    const int r0 = wp * 16 + gid;   // rows this thread owns: r0, r0+8

#pragma unroll
    for (int kt = 0; kt < 2; kt++) {
        const int i0 = kt * 8 + tig;
        // A-fragment: A_op[r,i] = A[i,r]   (A global: [16][64], L1-resident)
        unsigned aA[4];
        aA[0] = f2tf(__ldg(&Am[(i0    ) * RR + r0    ]));
        aA[1] = f2tf(__ldg(&Am[(i0    ) * RR + r0 + 8]));
        aA[2] = f2tf(__ldg(&Am[(i0 + 4) * RR + r0    ]));
        aA[3] = f2tf(__ldg(&Am[(i0 + 4) * RR + r0 + 8]));
#pragma unroll
        for (int nt = 0; nt < 8; nt++) {
            unsigned bx[2];
            bx[0] = x1s[(i0    ) * P1 + nt * 8 + gid];
            bx[1] = x1s[(i0 + 4) * P1 + nt * 8 + gid];
            mma_tf32(t1a[nt], aA, bx);
        }
        unsigned aB[4];
        aB[0] = f2tf(__ldg(&Bm[(i0    ) * RR + r0    ]));
        aB[1] = f2tf(__ldg(&Bm[(i0    ) * RR + r0 + 8]));
        aB[2] = f2tf(__ldg(&Bm[(i0 + 4) * RR + r0    ]));
        aB[3] = f2tf(__ldg(&Bm[(i0 + 4) * RR + r0 + 8]));
#pragma unroll
        for (int nt = 0; nt < 4; nt++) {
            unsigned bx[2];
            bx[0] = x2s[(i0    ) * P2 + nt * 8 + gid];
            bx[1] = x2s[(i0 + 4) * P2 + nt * 8 + gid];
            mma_tf32(t2a[nt], aB, bx);
        }
    }

    // ---- write t2 as tf32 hi+lo (error-free split of the intermediate) ----
#pragma unroll
    for (int nt = 0; nt < 4; nt++) {
        const int v0 = nt * 8 + 2 * tig;
#pragma unroll
        for (int h = 0; h < 2; h++) {           // h=0: row r0, h=1: row r0+8
            const int rr = r0 + 8 * h;
#pragma unroll
            for (int c = 0; c < 2; c++) {
                float v = t2a[nt][h * 2 + c];
                unsigned hb = f2tf(v);
                unsigned lb = f2tf(v - __uint_as_float(hb));
                t2hi[rr * PW + v0 + c] = hb;
                t2lo[rr * PW + v0 + c] = lb;
            }
        }
    }
    __syncwarp();

    // ---- stage B: t3[r,o] = sum_v t2[r,v] * w[o,v]  (K=32, split A operand) ----
    float t3a[8][4];
#pragma unroll
    for (int n = 0; n < 8; n++)
#pragma unroll
        for (int j = 0; j < 4; j++) t3a[n][j] = 0.f;

#pragma unroll
    for (int kt = 0; kt < 4; kt++) {
        const int v0 = kt * 8 + tig;
        unsigned aH[4], aL[4];
        aH[0] = t2hi[(r0    ) * PW + v0    ];
        aH[1] = t2hi[(r0 + 8) * PW + v0    ];
        aH[2] = t2hi[(r0    ) * PW + v0 + 4];
        aH[3] = t2hi[(r0 + 8) * PW + v0 + 4];
        aL[0] = t2lo[(r0    ) * PW + v0    ];
        aL[1] = t2lo[(r0 + 8) * PW + v0    ];
        aL[2] = t2lo[(r0    ) * PW + v0 + 4];
        aL[3] = t2lo[(r0 + 8) * PW + v0 + 4];
#pragma unroll
        for (int nt = 0; nt < 8; nt++) {
            unsigned bx[2];
            bx[0] = ws[(nt * 8 + gid) * PW + v0    ];
            bx[1] = ws[(nt * 8 + gid) * PW + v0 + 4];
            mma_tf32(t3a[nt], aH, bx);
            mma_tf32(t3a[nt], aL, bx);
        }
    }

    // ---- p = t1 * t3 in registers (fp32 exact), split to tf32 hi+lo ----
#pragma unroll
    for (int nt = 0; nt < 8; nt++) {
        const int o0 = nt * 8 + 2 * tig;
#pragma unroll
        for (int h = 0; h < 2; h++) {
            const int rr = r0 + 8 * h;
#pragma unroll
            for (int c = 0; c < 2; c++) {
                float v = t1a[nt][h * 2 + c] * t3a[nt][h * 2 + c];
                unsigned hb = f2tf(v);
                unsigned lb = f2tf(v - __uint_as_float(hb));
                phi[rr * P1 + o0 + c] = hb;
                plo[rr * P1 + o0 + c] = lb;
            }
        }
    }
    __syncthreads();

    // ---- stage C: out[c,o] = sum_r C[c,r] * p[r,o]  (M=16, K=64, split B) ----
    float oa[2][4];
#pragma unroll
    for (int n = 0; n < 2; n++)
#pragma unroll
        for (int j = 0; j < 4; j++) oa[n][j] = 0.f;

#pragma unroll
    for (int kt = 0; kt < 8; kt++) {
        const int rk = kt * 8 + tig;
        // A-fragment: C[c,r]  (C global: [16][64], L1-resident)
        unsigned aC[4];
        aC[0] = f2tf(__ldg(&Cm[(gid    ) * RR + rk    ]));
        aC[1] = f2tf(__ldg(&Cm[(gid + 8) * RR + rk    ]));
        aC[2] = f2tf(__ldg(&Cm[(gid    ) * RR + rk + 4]));
        aC[3] = f2tf(__ldg(&Cm[(gid + 8) * RR + rk + 4]));
#pragma unroll
        for (int j = 0; j < 2; j++) {
            const int nt = wp * 2 + j;          // warp owns o-tiles 2wp, 2wp+1
            unsigned bH[2], bL[2];
            bH[0] = phi[(rk    ) * P1 + nt * 8 + gid];
            bH[1] = phi[(rk + 4) * P1 + nt * 8 + gid];
            bL[0] = plo[(rk    ) * P1 + nt * 8 + gid];
            bL[1] = plo[(rk + 4) * P1 + nt * 8 + gid];
            mma_tf32(oa[j], aC, bH);
            mma_tf32(oa[j], aC, bL);
        }
    }

    // ---- store out[b][c][o] ----
    float* __restrict__ og = out + (size_t)b * (DD * CHO);
#pragma unroll
    for (int j = 0; j < 2; j++) {
        const int nt = wp * 2 + j;
        const int o0 = nt * 8 + 2 * tig;
        *(float2*)&og[(gid    ) * CHO + o0] = make_float2(oa[j][0], oa[j][1]);
        *(float2*)&og[(gid + 8) * CHO + o0] = make_float2(oa[j][2], oa[j][3]);
    }
}

extern "C" void kernel_launch(void* const* d_in, const int* in_sizes, int n_in,
                              void* d_out, int out_size)
{
    const float* x1 = (const float*)d_in[0];
    const float* x2 = (const float*)d_in[1];
    const float* w  = (const float*)d_in[2];
    const float* Am = (const float*)d_in[3];
    const float* Bm = (const float*)d_in[4];
    const float* Cm = (const float*)d_in[5];
    float* out = (float*)d_out;

    static bool attr_set = false;
    if (!attr_set) {
        cudaFuncSetAttribute(cp_tp_tf32,
                             cudaFuncAttributeMaxDynamicSharedMemorySize,
                             SMEM_WORDS * 4);
        attr_set = true;
    }
    cp_tp_tf32<<<NB, 128, SMEM_WORDS * 4>>>(x1, x2, w, Am, Bm, Cm, out);
}

// round 7
// speedup vs baseline: 3.0068x; 1.3231x over previous
#include <cuda_runtime.h>
#include <cstdint>

// Problem constants
#define NB      32768
#define DD      16
#define CH1     64
#define CH2     32
#define CHO     64
#define RR      64

// smem pitches (words)
#define PX   20   // x1p/x2p: [row][8 uint2 pairs] + pad
#define PWS  40   // wsp: [o][16 uint2 pairs], gid*40 mod 32 = gid*8 -> conflict-free uint2 reads
#define PT2  80   // t2p: [r][16 uint4] + pad, gid*80 mod 32 = gid*16 -> conflict-free uint4 reads
#define PP   72   // pP:  [o][32 uint2 pairs] + pad, gid*72 mod 32 = gid*8 -> conflict-free uint2 reads

// word offsets inside the static smem pool
#define OFF_T2   0                       // 64*80 = 5120 words (live: stage A-write .. stage B)
#define OFF_U    (OFF_T2 + RR * PT2)     // union region, 4608 words
#define OFF_X1   (OFF_U)                 // 64*20 = 1280   (live: stage 0 .. stage A)
#define OFF_X2   (OFF_X1 + CH1 * PX)     // 32*20 = 640    (live: stage 0 .. stage A)
#define OFF_W    (OFF_X2 + CH2 * PX)     // 64*40 = 2560   (live: stage 0 .. stage B)
#define OFF_P    (OFF_U)                 // 64*72 = 4608   (live: after stage-B barrier .. stage C)
#define SMEM_WORDS (OFF_U + CHO * PP)    // 9728 words = 38912 bytes (static, <48KB)

__device__ __forceinline__ unsigned f2tf(float x) {
    unsigned r;
    asm("cvt.rna.tf32.f32 %0, %1;" : "=r"(r) : "f"(x));
    return r;
}

__device__ __forceinline__ void mma_tf32(float* d, const unsigned* a, const unsigned* b) {
    asm volatile(
        "mma.sync.aligned.m16n8k8.row.col.f32.tf32.tf32.f32 "
        "{%0,%1,%2,%3}, {%4,%5,%6,%7}, {%8,%9}, {%0,%1,%2,%3};\n"
        : "+f"(d[0]), "+f"(d[1]), "+f"(d[2]), "+f"(d[3])
        : "r"(a[0]), "r"(a[1]), "r"(a[2]), "r"(a[3]), "r"(b[0]), "r"(b[1]));
}

// Pre-packed tf32 MMA fragments of A, B, C (batch-invariant), built once per launch.
__device__ uint4 g_fragA[2][128];   // [kt][tid]
__device__ uint4 g_fragB[2][128];
__device__ uint4 g_fragC[8][128];

__global__ void prep_frags(const float* __restrict__ Am,
                           const float* __restrict__ Bm,
                           const float* __restrict__ Cm)
{
    const int t    = threadIdx.x;      // 0..127
    const int lane = t & 31;
    const int wp   = t >> 5;
    const int gid  = lane >> 2;
    const int tig  = lane & 3;
    const int r0   = wp * 16 + gid;

#pragma unroll
    for (int kt = 0; kt < 2; kt++) {
        const int i0 = kt * 8 + tig;
        uint4 fa, fb;
        fa.x = f2tf(Am[(i0    ) * RR + r0    ]);
        fa.y = f2tf(Am[(i0    ) * RR + r0 + 8]);
        fa.z = f2tf(Am[(i0 + 4) * RR + r0    ]);
        fa.w = f2tf(Am[(i0 + 4) * RR + r0 + 8]);
        g_fragA[kt][t] = fa;
        fb.x = f2tf(Bm[(i0    ) * RR + r0    ]);
        fb.y = f2tf(Bm[(i0    ) * RR + r0 + 8]);
        fb.z = f2tf(Bm[(i0 + 4) * RR + r0    ]);
        fb.w = f2tf(Bm[(i0 + 4) * RR + r0 + 8]);
        g_fragB[kt][t] = fb;
    }
#pragma unroll
    for (int kt = 0; kt < 8; kt++) {
        const int rk = kt * 8 + tig;
        uint4 fc;
        fc.x = f2tf(Cm[(gid    ) * RR + rk    ]);
        fc.y = f2tf(Cm[(gid + 8) * RR + rk    ]);
        fc.z = f2tf(Cm[(gid    ) * RR + rk + 4]);
        fc.w = f2tf(Cm[(gid + 8) * RR + rk + 4]);
        g_fragC[kt][t] = fc;
    }
}

__global__ __launch_bounds__(128, 4)
void cp_tp_tf32(const float* __restrict__ x1,
                const float* __restrict__ x2,
                const float* __restrict__ w,
                float* __restrict__ out)
{
    __shared__ __align__(16) unsigned smpool[SMEM_WORDS];
    unsigned* t2p = smpool + OFF_T2;
    unsigned* x1p = smpool + OFF_X1;
    unsigned* x2p = smpool + OFF_X2;
    unsigned* wsp = smpool + OFF_W;
    unsigned* pP  = smpool + OFF_P;

    const int b    = blockIdx.x;
    const int t    = threadIdx.x;
    const int lane = t & 31;
    const int wp   = t >> 5;
    const int gid  = lane >> 2;
    const int tig  = lane & 3;
    const int r0   = wp * 16 + gid;

    const float* __restrict__ x1g = x1 + (size_t)b * (DD * CH1);
    const float* __restrict__ x2g = x2 + (size_t)b * (DD * CH2);
    const float* __restrict__ wg  = w  + (size_t)b * (CHO * CH2);

    // ---- stage 0: load inputs, convert to tf32, store pair-interleaved ----
    {   // x1: pairs (i, i+4), i in {0..3, 8..11}
        const int pi = t >> 4;                       // 0..7
        const int i0 = pi + ((pi >> 2) << 2);        // {0,1,2,3,8,9,10,11}
        const int o0 = (t & 15) * 4;
        float4 fa = *(const float4*)&x1g[(i0    ) * CH1 + o0];
        float4 fb = *(const float4*)&x1g[(i0 + 4) * CH1 + o0];
        const float* pa = &fa.x; const float* pb = &fb.x;
#pragma unroll
        for (int k = 0; k < 4; k++) {
            uint2 v = make_uint2(f2tf(pa[k]), f2tf(pb[k]));
            *(uint2*)&x1p[(o0 + k) * PX + pi * 2] = v;
        }
    }
    {   // x2
        const int i  = t >> 3;                       // 0..15
        const int v0 = (t & 7) * 4;
        const int pi = ((i & 8) >> 1) + (i & 3);     // pair index 0..7
        const int si = (i >> 2) & 1;                 // first/second of pair
        float4 f = *(const float4*)&x2g[i * CH2 + v0];
        const float* pf = &f.x;
#pragma unroll
        for (int k = 0; k < 4; k++)
            x2p[(v0 + k) * PX + pi * 2 + si] = f2tf(pf[k]);
    }
    {   // w: pairs (v, v+4) within each 8-block
#pragma unroll
        for (int task = t; task < 256; task += 128) {
            const int o  = task >> 2;
            const int vg = task & 3;
            float4 fa = *(const float4*)&wg[o * CH2 + vg * 8    ];
            float4 fb = *(const float4*)&wg[o * CH2 + vg * 8 + 4];
            const float* pa = &fa.x; const float* pb = &fb.x;
#pragma unroll
            for (int k = 0; k < 4; k++) {
                uint2 v = make_uint2(f2tf(pa[k]), f2tf(pb[k]));
                *(uint2*)&wsp[o * PWS + (vg * 4 + k) * 2] = v;
            }
        }
    }
    __syncthreads();

    // ---- stage A: t1 (16 MMA/warp) and t2 (8 MMA/warp), K=16 ----
    float t1a[8][4];
    float t2a[4][4];
#pragma unroll
    for (int n = 0; n < 8; n++)
#pragma unroll
        for (int j = 0; j < 4; j++) t1a[n][j] = 0.f;
#pragma unroll
    for (int n = 0; n < 4; n++)
#pragma unroll
        for (int j = 0; j < 4; j++) t2a[n][j] = 0.f;

#pragma unroll
    for (int kt = 0; kt < 2; kt++) {
        uint4 aA4 = g_fragA[kt][t];
        unsigned aA[4] = {aA4.x, aA4.y, aA4.z, aA4.w};
#pragma unroll
        for (int nt = 0; nt < 8; nt++) {
            uint2 bv = *(const uint2*)&x1p[(nt * 8 + gid) * PX + (kt * 4 + tig) * 2];
            unsigned bx[2] = {bv.x, bv.y};
            mma_tf32(t1a[nt], aA, bx);
        }
        uint4 aB4 = g_fragB[kt][t];
        unsigned aB[4] = {aB4.x, aB4.y, aB4.z, aB4.w};
#pragma unroll
        for (int nt = 0; nt < 4; nt++) {
            uint2 bv = *(const uint2*)&x2p[(nt * 8 + gid) * PX + (kt * 4 + tig) * 2];
            unsigned bx[2] = {bv.x, bv.y};
            mma_tf32(t2a[nt], aB, bx);
        }
    }

    // ---- t2 -> tf32 hi+lo, packed (hi,lo,hi+4,lo+4) per uint4 slot ----
#pragma unroll
    for (int nt = 0; nt < 4; nt++) {
#pragma unroll
        for (int h = 0; h < 2; h++) {
            const int r = r0 + 8 * h;
#pragma unroll
            for (int c = 0; c < 2; c++) {
                const int tv   = 2 * tig + c;         // v within 8-block
                const int pair = nt * 4 + (tv & 3);
                const int off  = (tv >> 2) * 2;
                float val = t2a[nt][h * 2 + c];
                unsigned hb = f2tf(val);
                unsigned lb = f2tf(val - __uint_as_float(hb));
                *(uint2*)&t2p[r * PT2 + pair * 4 + off] = make_uint2(hb, lb);
            }
        }
    }
    __syncwarp();   // t2p rows [wp*16, wp*16+16) are produced and consumed by this warp only

    // ---- stage B: t3[r,o] = sum_v t2[r,v]*w[o,v], K=32, split A (64 MMA/warp) ----
    float t3a[8][4];
#pragma unroll
    for (int n = 0; n < 8; n++)
#pragma unroll
        for (int j = 0; j < 4; j++) t3a[n][j] = 0.f;

#pragma unroll
    for (int kt = 0; kt < 4; kt++) {
        uint4 q0 = *(const uint4*)&t2p[(r0    ) * PT2 + (kt * 4 + tig) * 4];
        uint4 q1 = *(const uint4*)&t2p[(r0 + 8) * PT2 + (kt * 4 + tig) * 4];
        unsigned aH[4] = {q0.x, q1.x, q0.z, q1.z};
        unsigned aL[4] = {q0.y, q1.y, q0.w, q1.w};
#pragma unroll
        for (int nt = 0; nt < 8; nt++) {
            uint2 bv = *(const uint2*)&wsp[(nt * 8 + gid) * PWS + (kt * 4 + tig) * 2];
            unsigned bx[2] = {bv.x, bv.y};
            mma_tf32(t3a[nt], aH, bx);
            mma_tf32(t3a[nt], aL, bx);
        }
    }

    // all warps done reading x1p/x2p/wsp before pP overwrites the union region
    __syncthreads();

    // ---- p = t1*t3 (fp32), single tf32, packed as pairs (r, r+4) per 8-block ----
#pragma unroll
    for (int nt = 0; nt < 8; nt++) {
#pragma unroll
        for (int h = 0; h < 2; h++) {
            const int r    = r0 + 8 * h;
            const int pair = ((r >> 3) << 2) + (r & 3);
            const int sel  = (r >> 2) & 1;
#pragma unroll
            for (int c = 0; c < 2; c++) {
                const int o = nt * 8 + 2 * tig + c;
                float val = t1a[nt][h * 2 + c] * t3a[nt][h * 2 + c];
                pP[o * PP + pair * 2 + sel] = f2tf(val);
            }
        }
    }
    __syncthreads();

    // ---- stage C: out[c,o] = sum_r C[c,r]*p[r,o], K=64 (16 MMA/warp) ----
    float oa[2][4];
#pragma unroll
    for (int n = 0; n < 2; n++)
#pragma unroll
        for (int j = 0; j < 4; j++) oa[n][j] = 0.f;

#pragma unroll
    for (int kt = 0; kt < 8; kt++) {
        uint4 aC4 = g_fragC[kt][t];
        unsigned aC[4] = {aC4.x, aC4.y, aC4.z, aC4.w};
#pragma unroll
        for (int j = 0; j < 2; j++) {
            const int nt = wp * 2 + j;
            uint2 bv = *(const uint2*)&pP[(nt * 8 + gid) * PP + (kt * 4 + tig) * 2];
            unsigned bP[2] = {bv.x, bv.y};
            mma_tf32(oa[j], aC, bP);
        }
    }

    // ---- store out[b][c][o] ----
    float* __restrict__ og = out + (size_t)b * (DD * CHO);
#pragma unroll
    for (int j = 0; j < 2; j++) {
        const int nt = wp * 2 + j;
        const int o0 = nt * 8 + 2 * tig;
        *(float2*)&og[(gid    ) * CHO + o0] = make_float2(oa[j][0], oa[j][1]);
        *(float2*)&og[(gid + 8) * CHO + o0] = make_float2(oa[j][2], oa[j][3]);
    }
}

extern "C" void kernel_launch(void* const* d_in, const int* in_sizes, int n_in,
                              void* d_out, int out_size)
{
    const float* x1 = (const float*)d_in[0];
    const float* x2 = (const float*)d_in[1];
    const float* w  = (const float*)d_in[2];
    const float* Am = (const float*)d_in[3];
    const float* Bm = (const float*)d_in[4];
    const float* Cm = (const float*)d_in[5];
    float* out = (float*)d_out;

    prep_frags<<<1, 128>>>(Am, Bm, Cm);
    cp_tp_tf32<<<NB, 128>>>(x1, x2, w, out);
}

// round 14
// speedup vs baseline: 3.5566x; 1.1828x over previous
#include <cuda_runtime.h>
#include <cstdint>

// Problem constants
#define NB      32768
#define DD      16
#define CH1     64
#define CH2     32
#define CHO     64
#define RR      64

// smem pitches (words)
#define PX    20   // x1p/x2p: [row][8 uint2 pairs] + pad
#define PWS   40   // wsp: [o][16 uint2 pairs] + pad
#define PT2N  34   // t2p: [r][16 pairs = 32 words] + 2 pad; writes conflict-free, uint2 reads 2-way
#define PP    72   // pP:  [o][32 uint2 pairs] + pad

// word offsets inside the static smem pool
#define OFF_T2   0                        // 64*34 = 2176 words
#define OFF_U    (OFF_T2 + RR * PT2N)     // union region
#define OFF_X1   (OFF_U)                  // 64*20 = 1280 (live: stage0 .. stage A)
#define OFF_X2   (OFF_X1 + CH1 * PX)      // 32*20 = 640  (live: stage0 .. stage A)
#define OFF_W    (OFF_X2 + CH2 * PX)      // 64*40 = 2560 (live: stage0 .. stage B)
#define OFF_P    (OFF_U)                  // 64*72 = 4608 (live: post-B barrier .. stage C)
#define SMEM_WORDS (OFF_U + CHO * PP)     // 6784 words = 27136 bytes

__device__ __forceinline__ unsigned f2tf(float x) {
    unsigned r;
    asm("cvt.rna.tf32.f32 %0, %1;" : "=r"(r) : "f"(x));
    return r;
}

__device__ __forceinline__ void mma_tf32(float* d, const unsigned* a, const unsigned* b) {
    asm volatile(
        "mma.sync.aligned.m16n8k8.row.col.f32.tf32.tf32.f32 "
        "{%0,%1,%2,%3}, {%4,%5,%6,%7}, {%8,%9}, {%0,%1,%2,%3};\n"
        : "+f"(d[0]), "+f"(d[1]), "+f"(d[2]), "+f"(d[3])
        : "r"(a[0]), "r"(a[1]), "r"(a[2]), "r"(a[3]), "r"(b[0]), "r"(b[1]));
}

// Pre-packed tf32 MMA fragments of A, B, C (batch-invariant), built once per launch.
__device__ uint4 g_fragA[4][2][32];   // [r-tile][kt][lane]
__device__ uint4 g_fragB[4][2][32];
__device__ uint4 g_fragC[8][128];     // [kt][tid]

__global__ void prep_frags(const float* __restrict__ Am,
                           const float* __restrict__ Bm,
                           const float* __restrict__ Cm)
{
    const int t    = threadIdx.x;      // 0..127
    const int lane = t & 31;
    const int gid  = lane >> 2;
    const int tig  = lane & 3;

    if (t < 32) {
#pragma unroll
        for (int rt = 0; rt < 4; rt++) {
            const int rb = rt * 16 + gid;
#pragma unroll
            for (int kt = 0; kt < 2; kt++) {
                const int i0 = kt * 8 + tig;
                uint4 fa, fb;
                fa.x = f2tf(Am[(i0    ) * RR + rb    ]);
                fa.y = f2tf(Am[(i0    ) * RR + rb + 8]);
                fa.z = f2tf(Am[(i0 + 4) * RR + rb    ]);
                fa.w = f2tf(Am[(i0 + 4) * RR + rb + 8]);
                g_fragA[rt][kt][lane] = fa;
                fb.x = f2tf(Bm[(i0    ) * RR + rb    ]);
                fb.y = f2tf(Bm[(i0    ) * RR + rb + 8]);
                fb.z = f2tf(Bm[(i0 + 4) * RR + rb    ]);
                fb.w = f2tf(Bm[(i0 + 4) * RR + rb + 8]);
                g_fragB[rt][kt][lane] = fb;
            }
        }
    }
#pragma unroll
    for (int kt = 0; kt < 8; kt++) {
        const int rk = kt * 8 + tig;
        uint4 fc;
        fc.x = f2tf(Cm[(gid    ) * RR + rk    ]);
        fc.y = f2tf(Cm[(gid + 8) * RR + rk    ]);
        fc.z = f2tf(Cm[(gid    ) * RR + rk + 4]);
        fc.w = f2tf(Cm[(gid + 8) * RR + rk + 4]);
        g_fragC[kt][t] = fc;
    }
}

__global__ __launch_bounds__(128, 4)
void cp_tp_tf32(const float* __restrict__ x1,
                const float* __restrict__ x2,
                const float* __restrict__ w,
                float* __restrict__ out)
{
    __shared__ __align__(16) unsigned smpool[SMEM_WORDS];
    unsigned* t2p = smpool + OFF_T2;
    unsigned* x1p = smpool + OFF_X1;
    unsigned* x2p = smpool + OFF_X2;
    unsigned* wsp = smpool + OFF_W;
    unsigned* pP  = smpool + OFF_P;

    const int b    = blockIdx.x;
    const int t    = threadIdx.x;
    const int lane = t & 31;
    const int wp   = t >> 5;
    const int gid  = lane >> 2;
    const int tig  = lane & 3;

    const int wr = wp & 1;          // r-group: rows [wr*32, wr*32+32)
    const int wo = wp >> 1;         // o-group: cols [wo*32, wo*32+32); v-group [wo*16, +16)
    const int R0 = wr * 32;
    const int O0 = wo * 32;
    const int V0 = wo * 16;

    const float* __restrict__ x1g = x1 + (size_t)b * (DD * CH1);
    const float* __restrict__ x2g = x2 + (size_t)b * (DD * CH2);
    const float* __restrict__ wg  = w  + (size_t)b * (CHO * CH2);

    // ---- stage 0: load inputs, convert to tf32, store pair-interleaved ----
    {   // x1: pairs (i, i+4), i in {0..3, 8..11}
        const int pi = t >> 4;                       // 0..7
        const int i0 = pi + ((pi >> 2) << 2);        // {0,1,2,3,8,9,10,11}
        const int o0 = (t & 15) * 4;
        float4 fa = *(const float4*)&x1g[(i0    ) * CH1 + o0];
        float4 fb = *(const float4*)&x1g[(i0 + 4) * CH1 + o0];
        const float* pa = &fa.x; const float* pb = &fb.x;
#pragma unroll
        for (int k = 0; k < 4; k++) {
            uint2 v = make_uint2(f2tf(pa[k]), f2tf(pb[k]));
            *(uint2*)&x1p[(o0 + k) * PX + pi * 2] = v;
        }
    }
    {   // x2
        const int i  = t >> 3;                       // 0..15
        const int v0 = (t & 7) * 4;
        const int pi = ((i & 8) >> 1) + (i & 3);     // pair index 0..7
        const int si = (i >> 2) & 1;                 // first/second of pair
        float4 f = *(const float4*)&x2g[i * CH2 + v0];
        const float* pf = &f.x;
#pragma unroll
        for (int k = 0; k < 4; k++)
            x2p[(v0 + k) * PX + pi * 2 + si] = f2tf(pf[k]);
    }
    {   // w: pairs (v, v+4) within each 8-block
#pragma unroll
        for (int task = t; task < 256; task += 128) {
            const int o  = task >> 2;
            const int vg = task & 3;
            float4 fa = *(const float4*)&wg[o * CH2 + vg * 8    ];
            float4 fb = *(const float4*)&wg[o * CH2 + vg * 8 + 4];
            const float* pa = &fa.x; const float* pb = &fb.x;
#pragma unroll
            for (int k = 0; k < 4; k++) {
                uint2 v = make_uint2(f2tf(pa[k]), f2tf(pb[k]));
                *(uint2*)&wsp[o * PWS + (vg * 4 + k) * 2] = v;
            }
        }
    }
    __syncthreads();

    // ---- stage A: t1[R0..R0+31][O0..O0+31] (16 MMA), t2[R0..R0+31][V0..V0+15] (8 MMA) ----
    float t1a[2][4][4];
    float t2a[2][2][4];
#pragma unroll
    for (int m = 0; m < 2; m++)
#pragma unroll
        for (int n = 0; n < 4; n++)
#pragma unroll
            for (int j = 0; j < 4; j++) t1a[m][n][j] = 0.f;
#pragma unroll
    for (int m = 0; m < 2; m++)
#pragma unroll
        for (int n = 0; n < 2; n++)
#pragma unroll
            for (int j = 0; j < 4; j++) t2a[m][n][j] = 0.f;

#pragma unroll
    for (int kt = 0; kt < 2; kt++) {
        unsigned aA[2][4], aB[2][4];
#pragma unroll
        for (int mt = 0; mt < 2; mt++) {
            uint4 a4 = g_fragA[wr * 2 + mt][kt][lane];
            aA[mt][0] = a4.x; aA[mt][1] = a4.y; aA[mt][2] = a4.z; aA[mt][3] = a4.w;
            uint4 b4 = g_fragB[wr * 2 + mt][kt][lane];
            aB[mt][0] = b4.x; aB[mt][1] = b4.y; aB[mt][2] = b4.z; aB[mt][3] = b4.w;
        }
#pragma unroll
        for (int nt = 0; nt < 4; nt++) {
            uint2 bv = *(const uint2*)&x1p[(O0 + nt * 8 + gid) * PX + (kt * 4 + tig) * 2];
            unsigned bx[2] = {bv.x, bv.y};
#pragma unroll
            for (int mt = 0; mt < 2; mt++) mma_tf32(t1a[mt][nt], aA[mt], bx);
        }
#pragma unroll
        for (int nt = 0; nt < 2; nt++) {
            uint2 bv = *(const uint2*)&x2p[(V0 + nt * 8 + gid) * PX + (kt * 4 + tig) * 2];
            unsigned bx[2] = {bv.x, bv.y};
#pragma unroll
            for (int mt = 0; mt < 2; mt++) mma_tf32(t2a[mt][nt], aB[mt], bx);
        }
    }

    // ---- t2 -> single rna tf32, smem layout [r][pair p=(v&3)*4+(v>>3)][slot=(v>>2)&1] ----
#pragma unroll
    for (int mt = 0; mt < 2; mt++) {
#pragma unroll
        for (int nt = 0; nt < 2; nt++) {
#pragma unroll
            for (int h = 0; h < 2; h++) {
                const int r = R0 + mt * 16 + 8 * h + gid;
#pragma unroll
                for (int c = 0; c < 2; c++) {
                    const int v    = V0 + nt * 8 + 2 * tig + c;
                    const int pair = (v & 3) * 4 + (v >> 3);
                    const int slot = (v >> 2) & 1;
                    t2p[r * PT2N + pair * 2 + slot] = f2tf(t2a[mt][nt][h * 2 + c]);
                }
            }
        }
    }
    __syncthreads();   // t2 rows cross warps (v split by wo)

    // ---- stage B: t3[R0..+31][O0..+31] = sum_v t2[r,v] * w[o,v]  (32 MMA) ----
    float t3a[2][4][4];
#pragma unroll
    for (int m = 0; m < 2; m++)
#pragma unroll
        for (int n = 0; n < 4; n++)
#pragma unroll
            for (int j = 0; j < 4; j++) t3a[m][n][j] = 0.f;

#pragma unroll
    for (int kt = 0; kt < 4; kt++) {
        unsigned aT[2][4];
#pragma unroll
        for (int mt = 0; mt < 2; mt++) {
            const int r = R0 + mt * 16 + gid;
            uint2 u0 = *(const uint2*)&t2p[(r    ) * PT2N + (tig * 4 + kt) * 2];
            uint2 u1 = *(const uint2*)&t2p[(r + 8) * PT2N + (tig * 4 + kt) * 2];
            aT[mt][0] = u0.x; aT[mt][1] = u1.x; aT[mt][2] = u0.y; aT[mt][3] = u1.y;
        }
#pragma unroll
        for (int nt = 0; nt < 4; nt++) {
            uint2 bv = *(const uint2*)&wsp[(O0 + nt * 8 + gid) * PWS + (kt * 4 + tig) * 2];
            unsigned bx[2] = {bv.x, bv.y};
#pragma unroll
            for (int mt = 0; mt < 2; mt++) mma_tf32(t3a[mt][nt], aT[mt], bx);
        }
    }

    // all warps done reading x1p/x2p/wsp before pP overwrites the union region
    __syncthreads();

    // ---- p = t1*t3 (fp32), single tf32, pP[o][pair(r,r+4)] ----
#pragma unroll
    for (int mt = 0; mt < 2; mt++) {
#pragma unroll
        for (int nt = 0; nt < 4; nt++) {
#pragma unroll
            for (int h = 0; h < 2; h++) {
                const int r    = R0 + mt * 16 + 8 * h + gid;
                const int pair = ((r >> 3) << 2) + (r & 3);
                const int sel  = (r >> 2) & 1;
#pragma unroll
                for (int c = 0; c < 2; c++) {
                    const int o = O0 + nt * 8 + 2 * tig + c;
                    float val = t1a[mt][nt][h * 2 + c] * t3a[mt][nt][h * 2 + c];
                    pP[o * PP + pair * 2 + sel] = f2tf(val);
                }
            }
        }
    }
    __syncthreads();

    // ---- stage C: out[c,o] = sum_r C[c,r]*p[r,o], K=64 (16 MMA/warp) ----
    float oa[2][4];
#pragma unroll
    for (int n = 0; n < 2; n++)
#pragma unroll
        for (int j = 0; j < 4; j++) oa[n][j] = 0.f;

#pragma unroll
    for (int kt = 0; kt < 8; kt++) {
        uint4 aC4 = g_fragC[kt][t];
        unsigned aC[4] = {aC4.x, aC4.y, aC4.z, aC4.w};
#pragma unroll
        for (int j = 0; j < 2; j++) {
            const int nt = wp * 2 + j;
            uint2 bv = *(const uint2*)&pP[(nt * 8 + gid) * PP + (kt * 4 + tig) * 2];
            unsigned bP[2] = {bv.x, bv.y};
            mma_tf32(oa[j], aC, bP);
        }
    }

    // ---- store out[b][c][o] ----
    float* __restrict__ og = out + (size_t)b * (DD * CHO);
#pragma unroll
    for (int j = 0; j < 2; j++) {
        const int nt = wp * 2 + j;
        const int o0 = nt * 8 + 2 * tig;
        *(float2*)&og[(gid    ) * CHO + o0] = make_float2(oa[j][0], oa[j][1]);
        *(float2*)&og[(gid + 8) * CHO + o0] = make_float2(oa[j][2], oa[j][3]);
    }
}

extern "C" void kernel_launch(void* const* d_in, const int* in_sizes, int n_in,
                              void* d_out, int out_size)
{
    const float* x1 = (const float*)d_in[0];
    const float* x2 = (const float*)d_in[1];
    const float* w  = (const float*)d_in[2];
    const float* Am = (const float*)d_in[3];
    const float* Bm = (const float*)d_in[4];
    const float* Cm = (const float*)d_in[5];
    float* out = (float*)d_out;

    prep_frags<<<1, 128>>>(Am, Bm, Cm);
    cp_tp_tf32<<<NB, 128>>>(x1, x2, w, out);
}

// round 17
// speedup vs baseline: 4.5307x; 1.2739x over previous
#include <cuda_runtime.h>
#include <cstdint>

// Problem constants
#define NB      32768
#define DD      16
#define CH1     64
#define CH2     32
#define CHO     64
#define RR      64

// smem pitches (words) — all verified conflict-free per 16/32/8-lane phase model
#define PX1   72   // x1p [i][o]:  stores STS.128 (8i+4oq), reads LDS.32 (8tig+gid)
#define PX2   40   // x2p [i][v]:  same structure
#define PW    36   // wsp [o][v]:  stores STS.128 (4o+8vg), reads LDS.32 (4gid+tig)
#define PT2N  34   // t2p pair-packed (unchanged): stores STS.32 free, reads LDS.64 free
#define PPN   72   // pP  [r][o]:  stores STS.64 (8gid+2tig), reads LDS.32 (8tig+gid)

// word offsets inside the static smem pool
#define OFF_T2   0                        // 64*34 = 2176 words
#define OFF_U    (OFF_T2 + RR * PT2N)     // union region
#define OFF_X1   (OFF_U)                  // 16*72 = 1152 (live: stage0 .. stage A)
#define OFF_X2   (OFF_X1 + DD * PX1)      // 16*40 = 640  (live: stage0 .. stage A)
#define OFF_W    (OFF_X2 + DD * PX2)      // 64*36 = 2304 (live: stage0 .. stage B)
#define OFF_P    (OFF_U)                  // 64*72 = 4608 (live: post-B barrier .. stage C)
#define SMEM_WORDS (OFF_U + RR * PPN)     // 2176 + 4608 = 6784 words = 27136 bytes

__device__ __forceinline__ unsigned f2tf(float x) {
    unsigned r;
    asm("cvt.rna.tf32.f32 %0, %1;" : "=r"(r) : "f"(x));
    return r;
}

__device__ __forceinline__ void mma_tf32(float* d, const unsigned* a, const unsigned* b) {
    asm volatile(
        "mma.sync.aligned.m16n8k8.row.col.f32.tf32.tf32.f32 "
        "{%0,%1,%2,%3}, {%4,%5,%6,%7}, {%8,%9}, {%0,%1,%2,%3};\n"
        : "+f"(d[0]), "+f"(d[1]), "+f"(d[2]), "+f"(d[3])
        : "r"(a[0]), "r"(a[1]), "r"(a[2]), "r"(a[3]), "r"(b[0]), "r"(b[1]));
}

// Pre-packed tf32 MMA fragments of A, B, C (batch-invariant), built once per launch.
__device__ uint4 g_fragA[4][2][32];   // [r-tile][kt][lane]
__device__ uint4 g_fragB[4][2][32];
__device__ uint4 g_fragC[8][128];     // [kt][tid]

__global__ void prep_frags(const float* __restrict__ Am,
                           const float* __restrict__ Bm,
                           const float* __restrict__ Cm)
{
    const int t    = threadIdx.x;      // 0..127
    const int lane = t & 31;
    const int gid  = lane >> 2;
    const int tig  = lane & 3;

    if (t < 32) {
#pragma unroll
        for (int rt = 0; rt < 4; rt++) {
            const int rb = rt * 16 + gid;
#pragma unroll
            for (int kt = 0; kt < 2; kt++) {
                const int i0 = kt * 8 + tig;
                uint4 fa, fb;
                fa.x = f2tf(Am[(i0    ) * RR + rb    ]);
                fa.y = f2tf(Am[(i0    ) * RR + rb + 8]);
                fa.z = f2tf(Am[(i0 + 4) * RR + rb    ]);
                fa.w = f2tf(Am[(i0 + 4) * RR + rb + 8]);
                g_fragA[rt][kt][lane] = fa;
                fb.x = f2tf(Bm[(i0    ) * RR + rb    ]);
                fb.y = f2tf(Bm[(i0    ) * RR + rb + 8]);
                fb.z = f2tf(Bm[(i0 + 4) * RR + rb    ]);
                fb.w = f2tf(Bm[(i0 + 4) * RR + rb + 8]);
                g_fragB[rt][kt][lane] = fb;
            }
        }
    }
#pragma unroll
    for (int kt = 0; kt < 8; kt++) {
        const int rk = kt * 8 + tig;
        uint4 fc;
        fc.x = f2tf(Cm[(gid    ) * RR + rk    ]);
        fc.y = f2tf(Cm[(gid + 8) * RR + rk    ]);
        fc.z = f2tf(Cm[(gid    ) * RR + rk + 4]);
        fc.w = f2tf(Cm[(gid + 8) * RR + rk + 4]);
        g_fragC[kt][t] = fc;
    }
}

__global__ __launch_bounds__(128, 4)
void cp_tp_tf32(const float* __restrict__ x1,
                const float* __restrict__ x2,
                const float* __restrict__ w,
                float* __restrict__ out)
{
    __shared__ __align__(16) unsigned smpool[SMEM_WORDS];
    unsigned* t2p = smpool + OFF_T2;
    unsigned* x1p = smpool + OFF_X1;
    unsigned* x2p = smpool + OFF_X2;
    unsigned* wsp = smpool + OFF_W;
    unsigned* pP  = smpool + OFF_P;

    const int b    = blockIdx.x;
    const int t    = threadIdx.x;
    const int lane = t & 31;
    const int wp   = t >> 5;
    const int gid  = lane >> 2;
    const int tig  = lane & 3;

    const int wr = wp & 1;          // r-group: rows [wr*32, wr*32+32)
    const int wo = wp >> 1;         // o-group: cols [wo*32, wo*32+32); v-group [wo*16, +16)
    const int R0 = wr * 32;
    const int O0 = wo * 32;
    const int V0 = wo * 16;

    const float* __restrict__ x1g = x1 + (size_t)b * (DD * CH1);
    const float* __restrict__ x2g = x2 + (size_t)b * (DD * CH2);
    const float* __restrict__ wg  = w  + (size_t)b * (CHO * CH2);

    // ---- stage 0: coalesced loads, convert to tf32, plain row-major stores ----
    {   // x1 [i][o]: thread (i = t>>3, oq = t&7) stores 2 STS.128
        const int i  = t >> 3;
        const int oq = t & 7;
#pragma unroll
        for (int half = 0; half < 2; half++) {
            const int o0 = (oq + half * 8) * 4;
            float4 f = *(const float4*)&x1g[i * CH1 + o0];
            uint4 u = make_uint4(f2tf(f.x), f2tf(f.y), f2tf(f.z), f2tf(f.w));
            *(uint4*)&x1p[i * PX1 + o0] = u;
        }
    }
    {   // x2 [i][v]: thread (i = t>>3, vq = t&7) stores 1 STS.128
        const int i  = t >> 3;
        const int vq = t & 7;
        float4 f = *(const float4*)&x2g[i * CH2 + vq * 4];
        uint4 u = make_uint4(f2tf(f.x), f2tf(f.y), f2tf(f.z), f2tf(f.w));
        *(uint4*)&x2p[i * PX2 + vq * 4] = u;
    }
    {   // w [o][v]: thread (o = t>>2 (+32), vg = t&3) stores 2x2 STS.128
#pragma unroll
        for (int it = 0; it < 2; it++) {
            const int o  = (t >> 2) + it * 32;
            const int vg = t & 3;
            float4 fa = *(const float4*)&wg[o * CH2 + vg * 8    ];
            float4 fb = *(const float4*)&wg[o * CH2 + vg * 8 + 4];
            uint4 ua = make_uint4(f2tf(fa.x), f2tf(fa.y), f2tf(fa.z), f2tf(fa.w));
            uint4 ub = make_uint4(f2tf(fb.x), f2tf(fb.y), f2tf(fb.z), f2tf(fb.w));
            *(uint4*)&wsp[o * PW + vg * 8    ] = ua;
            *(uint4*)&wsp[o * PW + vg * 8 + 4] = ub;
        }
    }
    __syncthreads();

    // ---- stage A: t1[R0..+31][O0..+31] (16 MMA), t2[R0..+31][V0..+15] (8 MMA) ----
    float t1a[2][4][4];
    float t2a[2][2][4];
#pragma unroll
    for (int m = 0; m < 2; m++)
#pragma unroll
        for (int n = 0; n < 4; n++)
#pragma unroll
            for (int j = 0; j < 4; j++) t1a[m][n][j] = 0.f;
#pragma unroll
    for (int m = 0; m < 2; m++)
#pragma unroll
        for (int n = 0; n < 2; n++)
#pragma unroll
            for (int j = 0; j < 4; j++) t2a[m][n][j] = 0.f;

#pragma unroll
    for (int kt = 0; kt < 2; kt++) {
        const int i0 = kt * 8 + tig;
        unsigned aA[2][4], aB[2][4];
#pragma unroll
        for (int mt = 0; mt < 2; mt++) {
            uint4 a4 = g_fragA[wr * 2 + mt][kt][lane];
            aA[mt][0] = a4.x; aA[mt][1] = a4.y; aA[mt][2] = a4.z; aA[mt][3] = a4.w;
            uint4 b4 = g_fragB[wr * 2 + mt][kt][lane];
            aB[mt][0] = b4.x; aB[mt][1] = b4.y; aB[mt][2] = b4.z; aB[mt][3] = b4.w;
        }
#pragma unroll
        for (int nt = 0; nt < 4; nt++) {
            unsigned bx[2];
            bx[0] = x1p[(i0    ) * PX1 + O0 + nt * 8 + gid];   // 8tig+gid: free
            bx[1] = x1p[(i0 + 4) * PX1 + O0 + nt * 8 + gid];
#pragma unroll
            for (int mt = 0; mt < 2; mt++) mma_tf32(t1a[mt][nt], aA[mt], bx);
        }
#pragma unroll
        for (int nt = 0; nt < 2; nt++) {
            unsigned bx[2];
            bx[0] = x2p[(i0    ) * PX2 + V0 + nt * 8 + gid];
            bx[1] = x2p[(i0 + 4) * PX2 + V0 + nt * 8 + gid];
#pragma unroll
            for (int mt = 0; mt < 2; mt++) mma_tf32(t2a[mt][nt], aB[mt], bx);
        }
    }

    // ---- t2 -> single rna tf32, pair-packed layout (unchanged, verified free) ----
#pragma unroll
    for (int mt = 0; mt < 2; mt++) {
#pragma unroll
        for (int nt = 0; nt < 2; nt++) {
#pragma unroll
            for (int h = 0; h < 2; h++) {
                const int r = R0 + mt * 16 + 8 * h + gid;
#pragma unroll
                for (int c = 0; c < 2; c++) {
                    const int v    = V0 + nt * 8 + 2 * tig + c;
                    const int pair = (v & 3) * 4 + (v >> 3);
                    const int slot = (v >> 2) & 1;
                    t2p[r * PT2N + pair * 2 + slot] = f2tf(t2a[mt][nt][h * 2 + c]);
                }
            }
        }
    }
    __syncthreads();   // t2 rows cross warps (v split by wo)

    // ---- stage B: t3[R0..+31][O0..+31] = sum_v t2[r,v] * w[o,v]  (32 MMA) ----
    float t3a[2][4][4];
#pragma unroll
    for (int m = 0; m < 2; m++)
#pragma unroll
        for (int n = 0; n < 4; n++)
#pragma unroll
            for (int j = 0; j < 4; j++) t3a[m][n][j] = 0.f;

#pragma unroll
    for (int kt = 0; kt < 4; kt++) {
        unsigned aT[2][4];
#pragma unroll
        for (int mt = 0; mt < 2; mt++) {
            const int r = R0 + mt * 16 + gid;
            uint2 u0 = *(const uint2*)&t2p[(r    ) * PT2N + (tig * 4 + kt) * 2];
            uint2 u1 = *(const uint2*)&t2p[(r + 8) * PT2N + (tig * 4 + kt) * 2];
            aT[mt][0] = u0.x; aT[mt][1] = u1.x; aT[mt][2] = u0.y; aT[mt][3] = u1.y;
        }
#pragma unroll
        for (int nt = 0; nt < 4; nt++) {
            const int orow = O0 + nt * 8 + gid;
            unsigned bx[2];
            bx[0] = wsp[orow * PW + kt * 8 + tig    ];     // 4gid+tig: free
            bx[1] = wsp[orow * PW + kt * 8 + tig + 4];
#pragma unroll
            for (int mt = 0; mt < 2; mt++) mma_tf32(t3a[mt][nt], aT[mt], bx);
        }
    }

    // all warps done reading x1p/x2p/wsp before pP overwrites the union region
    __syncthreads();

    // ---- p = t1*t3 (fp32), single tf32, plain pP[r][o], uint2 c-pair stores ----
#pragma unroll
    for (int mt = 0; mt < 2; mt++) {
#pragma unroll
        for (int nt = 0; nt < 4; nt++) {
#pragma unroll
            for (int h = 0; h < 2; h++) {
                const int r  = R0 + mt * 16 + 8 * h + gid;
                const int o0 = O0 + nt * 8 + 2 * tig;
                uint2 v;
                v.x = f2tf(t1a[mt][nt][h * 2 + 0] * t3a[mt][nt][h * 2 + 0]);
                v.y = f2tf(t1a[mt][nt][h * 2 + 1] * t3a[mt][nt][h * 2 + 1]);
                *(uint2*)&pP[r * PPN + o0] = v;            // 8gid+2tig: free
            }
        }
    }
    __syncthreads();

    // ---- stage C: out[c,o] = sum_r C[c,r]*p[r,o], K=64 (16 MMA/warp) ----
    float oa[2][4];
#pragma unroll
    for (int n = 0; n < 2; n++)
#pragma unroll
        for (int j = 0; j < 4; j++) oa[n][j] = 0.f;

#pragma unroll
    for (int kt = 0; kt < 8; kt++) {
        const int rk = kt * 8 + tig;
        uint4 aC4 = g_fragC[kt][t];
        unsigned aC[4] = {aC4.x, aC4.y, aC4.z, aC4.w};
#pragma unroll
        for (int j = 0; j < 2; j++) {
            const int nt = wp * 2 + j;
            unsigned bP[2];
            bP[0] = pP[(rk    ) * PPN + nt * 8 + gid];     // 8tig+gid: free
            bP[1] = pP[(rk + 4) * PPN + nt * 8 + gid];
            mma_tf32(oa[j], aC, bP);
        }
    }

    // ---- store out[b][c][o] ----
    float* __restrict__ og = out + (size_t)b * (DD * CHO);
#pragma unroll
    for (int j = 0; j < 2; j++) {
        const int nt = wp * 2 + j;
        const int o0 = nt * 8 + 2 * tig;
        *(float2*)&og[(gid    ) * CHO + o0] = make_float2(oa[j][0], oa[j][1]);
        *(float2*)&og[(gid + 8) * CHO + o0] = make_float2(oa[j][2], oa[j][3]);
    }
}

extern "C" void kernel_launch(void* const* d_in, const int* in_sizes, int n_in,
                              void* d_out, int out_size)
{
    const float* x1 = (const float*)d_in[0];
    const float* x2 = (const float*)d_in[1];
    const float* w  = (const float*)d_in[2];
    const float* Am = (const float*)d_in[3];
    const float* Bm = (const float*)d_in[4];
    const float* Cm = (const float*)d_in[5];
    float* out = (float*)d_out;

    prep_frags<<<1, 128>>>(Am, Bm, Cm);
    cp_tp_tf32<<<NB, 128>>>(x1, x2, w, out);
}